// round 6
// baseline (speedup 1.0000x reference)
#include <cuda_runtime.h>
#include <math.h>

// ---------------------------------------------------------------------------
// Problem constants
// ---------------------------------------------------------------------------
#define Bq    1024      // batch
#define NF    128       // n_feat
#define D     256       // d_main
#define DI    512       // d_int
#define NC    100000    // n candidates
#define CTX   96        // context size (top-k)
#define NCLS  10
#define CAPK  3584      // top-k candidate buffer capacity (smem)

// ---------------------------------------------------------------------------
// Device scratch
// ---------------------------------------------------------------------------
__device__ float g_h1  [(size_t)NC * D];
__device__ float g_ki  [(size_t)NC * D];
__device__ float g_nn  [NC];
__device__ float g_x   [Bq * D];
__device__ float g_k   [Bq * D];
__device__ float g_kk  [Bq];
__device__ float g_d2  [(size_t)Bq * NC];
__device__ int   g_I   [Bq * CTX];
__device__ int   g_cls [Bq * CTX];
__device__ float g_S   [Bq * CTX];
__device__ float g_w   [Bq * CTX];
__device__ float g_diff[(size_t)Bq * CTX * D];
__device__ float g_mh  [(size_t)Bq * CTX * DI];
__device__ float g_V   [(size_t)Bq * CTX * D];
__device__ float g_xr  [Bq * D];
__device__ float g_ln  [Bq * D];
__device__ float g_p1  [Bq * DI];
__device__ float g_x2  [Bq * D];

// ---------------------------------------------------------------------------
// Double-buffered SGEMM (NN): C = act(A[M,K] @ B[K,N] + bias + addsrc)
// BM=BN=128, BK=8, 256 threads, 8x8 per-thread, smem rows padded to 136
// floats (544B: 16B-aligned rows -> LDS.128 in the inner loop).
// K % 8 == 0, N % 128 == 0 (all NN uses: N=256/512). M guarded.
// ---------------------------------------------------------------------------
__global__ void __launch_bounds__(256) sgemm_nn(
    int M, int N, int K,
    const float* __restrict__ A, const float* __restrict__ Bm,
    const float* __restrict__ bias, const float* __restrict__ addsrc,
    float* __restrict__ C, int relu)
{
    __shared__ float As[2][8][136];
    __shared__ float Bs[2][8][136];
    const int t  = threadIdx.x;
    const int m0 = blockIdx.y * 128;
    const int n0 = blockIdx.x * 128;
    const int tx = t & 15, ty = t >> 4;
    const int arow = t >> 1, acol = (t & 1) * 4;
    const int brow = t >> 5, bcol = (t & 31) * 4;
    const int gm_a = m0 + arow;

    float acc[8][8];
#pragma unroll
    for (int i = 0; i < 8; i++)
#pragma unroll
        for (int j = 0; j < 8; j++) acc[i][j] = 0.f;

    // preload tile 0
    {
        float4 av = make_float4(0.f, 0.f, 0.f, 0.f);
        if (gm_a < M)
            av = *reinterpret_cast<const float4*>(A + (size_t)gm_a * K + acol);
        As[0][acol + 0][arow] = av.x; As[0][acol + 1][arow] = av.y;
        As[0][acol + 2][arow] = av.z; As[0][acol + 3][arow] = av.w;
        float4 bv = *reinterpret_cast<const float4*>(Bm + (size_t)brow * N + n0 + bcol);
        *reinterpret_cast<float4*>(&Bs[0][brow][bcol]) = bv;
    }
    __syncthreads();

    const int ntiles = K >> 3;
    int buf = 0;
    for (int tt = 0; tt < ntiles; tt++) {
        float4 avn = make_float4(0.f, 0.f, 0.f, 0.f);
        float4 bvn;
        const bool more = (tt + 1 < ntiles);
        if (more) {
            const int k0 = (tt + 1) << 3;
            if (gm_a < M)
                avn = *reinterpret_cast<const float4*>(A + (size_t)gm_a * K + k0 + acol);
            bvn = *reinterpret_cast<const float4*>(Bm + (size_t)(k0 + brow) * N + n0 + bcol);
        }

#pragma unroll
        for (int kk = 0; kk < 8; kk++) {
            float4 a0 = *reinterpret_cast<const float4*>(&As[buf][kk][ty * 8]);
            float4 a1 = *reinterpret_cast<const float4*>(&As[buf][kk][ty * 8 + 4]);
            float4 b0 = *reinterpret_cast<const float4*>(&Bs[buf][kk][tx * 8]);
            float4 b1 = *reinterpret_cast<const float4*>(&Bs[buf][kk][tx * 8 + 4]);
            float a[8] = {a0.x, a0.y, a0.z, a0.w, a1.x, a1.y, a1.z, a1.w};
            float b[8] = {b0.x, b0.y, b0.z, b0.w, b1.x, b1.y, b1.z, b1.w};
#pragma unroll
            for (int i = 0; i < 8; i++)
#pragma unroll
                for (int j = 0; j < 8; j++)
                    acc[i][j] = fmaf(a[i], b[j], acc[i][j]);
        }

        if (more) {
            const int nb = buf ^ 1;
            As[nb][acol + 0][arow] = avn.x; As[nb][acol + 1][arow] = avn.y;
            As[nb][acol + 2][arow] = avn.z; As[nb][acol + 3][arow] = avn.w;
            *reinterpret_cast<float4*>(&Bs[nb][brow][bcol]) = bvn;
            __syncthreads();
            buf = nb;
        }
    }

#pragma unroll
    for (int i = 0; i < 8; i++) {
        int gm = m0 + ty * 8 + i;
        if (gm >= M) continue;
#pragma unroll
        for (int j = 0; j < 8; j++) {
            int gn = n0 + tx * 8 + j;
            float v = acc[i][j];
            if (bias)   v += bias[gn];
            if (addsrc) v += addsrc[(size_t)gm * N + gn];
            if (relu)   v = fmaxf(v, 0.f);
            C[(size_t)gm * N + gn] = v;
        }
    }
}

// ---------------------------------------------------------------------------
// Double-buffered distance GEMM (NT):
// C[m,n] = |a_m|^2 + |b_n|^2 - 2 * dot(A[m,:], Bt[n,:])
// A: [M,K] row-major, Bt: [N,K] row-major. K % 8 == 0. M,N guarded.
// ---------------------------------------------------------------------------
__global__ void __launch_bounds__(256) dist_nt(
    int M, int N, int K,
    const float* __restrict__ A, const float* __restrict__ Bt,
    const float* __restrict__ an2, const float* __restrict__ bn2,
    float* __restrict__ C)
{
    __shared__ float As[2][8][136];
    __shared__ float Bs[2][8][136];
    const int t  = threadIdx.x;
    const int m0 = blockIdx.y * 128;
    const int n0 = blockIdx.x * 128;
    const int tx = t & 15, ty = t >> 4;
    const int arow = t >> 1, acol = (t & 1) * 4;
    const int brow = t >> 1, bcol = (t & 1) * 4;
    const int gm_a = m0 + arow;
    const int gn_b = n0 + brow;

    float acc[8][8];
#pragma unroll
    for (int i = 0; i < 8; i++)
#pragma unroll
        for (int j = 0; j < 8; j++) acc[i][j] = 0.f;

    // preload tile 0
    {
        float4 av = make_float4(0.f, 0.f, 0.f, 0.f);
        if (gm_a < M)
            av = *reinterpret_cast<const float4*>(A + (size_t)gm_a * K + acol);
        As[0][acol + 0][arow] = av.x; As[0][acol + 1][arow] = av.y;
        As[0][acol + 2][arow] = av.z; As[0][acol + 3][arow] = av.w;
        float4 bv = make_float4(0.f, 0.f, 0.f, 0.f);
        if (gn_b < N)
            bv = *reinterpret_cast<const float4*>(Bt + (size_t)gn_b * K + bcol);
        Bs[0][bcol + 0][brow] = bv.x; Bs[0][bcol + 1][brow] = bv.y;
        Bs[0][bcol + 2][brow] = bv.z; Bs[0][bcol + 3][brow] = bv.w;
    }
    __syncthreads();

    const int ntiles = K >> 3;
    int buf = 0;
    for (int tt = 0; tt < ntiles; tt++) {
        float4 avn = make_float4(0.f, 0.f, 0.f, 0.f);
        float4 bvn = make_float4(0.f, 0.f, 0.f, 0.f);
        const bool more = (tt + 1 < ntiles);
        if (more) {
            const int k0 = (tt + 1) << 3;
            if (gm_a < M)
                avn = *reinterpret_cast<const float4*>(A + (size_t)gm_a * K + k0 + acol);
            if (gn_b < N)
                bvn = *reinterpret_cast<const float4*>(Bt + (size_t)gn_b * K + k0 + bcol);
        }

#pragma unroll
        for (int kk = 0; kk < 8; kk++) {
            float4 a0 = *reinterpret_cast<const float4*>(&As[buf][kk][ty * 8]);
            float4 a1 = *reinterpret_cast<const float4*>(&As[buf][kk][ty * 8 + 4]);
            float4 b0 = *reinterpret_cast<const float4*>(&Bs[buf][kk][tx * 8]);
            float4 b1 = *reinterpret_cast<const float4*>(&Bs[buf][kk][tx * 8 + 4]);
            float a[8] = {a0.x, a0.y, a0.z, a0.w, a1.x, a1.y, a1.z, a1.w};
            float b[8] = {b0.x, b0.y, b0.z, b0.w, b1.x, b1.y, b1.z, b1.w};
#pragma unroll
            for (int i = 0; i < 8; i++)
#pragma unroll
                for (int j = 0; j < 8; j++)
                    acc[i][j] = fmaf(a[i], b[j], acc[i][j]);
        }

        if (more) {
            const int nb = buf ^ 1;
            As[nb][acol + 0][arow] = avn.x; As[nb][acol + 1][arow] = avn.y;
            As[nb][acol + 2][arow] = avn.z; As[nb][acol + 3][arow] = avn.w;
            Bs[nb][bcol + 0][brow] = bvn.x; Bs[nb][bcol + 1][brow] = bvn.y;
            Bs[nb][bcol + 2][brow] = bvn.z; Bs[nb][bcol + 3][brow] = bvn.w;
            __syncthreads();
            buf = nb;
        }
    }

#pragma unroll
    for (int i = 0; i < 8; i++) {
        int gm = m0 + ty * 8 + i;
        if (gm >= M) continue;
        float a2 = an2[gm];
#pragma unroll
        for (int j = 0; j < 8; j++) {
            int gn = n0 + tx * 8 + j;
            if (gn >= N) continue;
            C[(size_t)gm * N + gn] = a2 + bn2[gn] - 2.f * acc[i][j];
        }
    }
}

// ---------------------------------------------------------------------------
// Row squared norms
// ---------------------------------------------------------------------------
__global__ void rownorm2(const float* __restrict__ X, float* __restrict__ out)
{
    int r = blockIdx.x, t = threadIdx.x;
    float v = X[(size_t)r * D + t];
    __shared__ float red[256];
    red[t] = v * v;
    __syncthreads();
    for (int k = 128; k > 0; k >>= 1) {
        if (t < k) red[t] += red[t + k];
        __syncthreads();
    }
    if (t == 0) out[r] = red[0];
}

// ---------------------------------------------------------------------------
// Top-96 smallest per row via histogram radix-select (unchanged, correct).
// ---------------------------------------------------------------------------
__device__ __forceinline__ unsigned f2u(float f) {
    unsigned u = __float_as_uint(f);
    return (u & 0x80000000u) ? ~u : (u | 0x80000000u);
}

__global__ void __launch_bounds__(256) topk_kernel(
    const float* __restrict__ D2, int N, int* __restrict__ I)
{
    const int row = blockIdx.x;
    const float* __restrict__ drow = D2 + (size_t)row * N;
    const int t = threadIdx.x;

    __shared__ unsigned hist[4096];
    __shared__ unsigned bufKey[CAPK];
    __shared__ int      bufIdx[CAPK];
    __shared__ unsigned pref[256];
    __shared__ unsigned long long red[256];
    __shared__ int sh_b1, sh_b2, sh_before, sh_nOut, sh_nBuf;

    for (int i = t; i < 4096; i += 256) hist[i] = 0;
    __syncthreads();
    for (int i = t; i < N; i += 256)
        atomicAdd(&hist[f2u(drow[i]) >> 20], 1u);
    __syncthreads();

    unsigned ls = 0;
#pragma unroll
    for (int j = 0; j < 16; j++) ls += hist[t * 16 + j];
    pref[t] = ls;
    __syncthreads();
    if (t == 0) {
        unsigned run = 0;
        for (int i = 0; i < 256; i++) { unsigned s = pref[i]; pref[i] = run; run += s; }
    }
    __syncthreads();
    {
        unsigned run = pref[t];
#pragma unroll
        for (int j = 0; j < 16; j++) {
            unsigned c = hist[t * 16 + j];
            if (run <= 95u && 95u < run + c) { sh_b1 = t * 16 + j; sh_before = (int)run; }
            run += c;
        }
    }
    __syncthreads();
    const int b1 = sh_b1;
    int before = sh_before;
    const unsigned cnt_b1 = hist[b1];
    __syncthreads();

    const int use2 = (cnt_b1 > CAPK);
    int b2 = -1;
    if (use2) {
        hist[t] = 0;
        __syncthreads();
        for (int i = t; i < N; i += 256) {
            unsigned k = f2u(drow[i]);
            if ((int)(k >> 20) == b1) atomicAdd(&hist[(k >> 12) & 255u], 1u);
        }
        __syncthreads();
        if (t == 0) {
            unsigned run = 0;
            unsigned tgt = (unsigned)(95 - before);
            for (int i = 0; i < 256; i++) {
                unsigned c = hist[i];
                if (run <= tgt && tgt < run + c) { sh_b2 = i; sh_before = before + (int)run; break; }
                run += c;
            }
        }
        __syncthreads();
        b2 = sh_b2;
        before = sh_before;
    }

    if (t == 0) { sh_nOut = 0; sh_nBuf = 0; }
    __syncthreads();
    for (int i = t; i < N; i += 256) {
        unsigned k = f2u(drow[i]);
        unsigned hb = k >> 20;
        bool less, eq;
        if (!use2) {
            less = hb < (unsigned)b1; eq = (hb == (unsigned)b1);
        } else {
            unsigned sb = (k >> 12) & 255u;
            less = (hb < (unsigned)b1) || (hb == (unsigned)b1 && sb < (unsigned)b2);
            eq   = (hb == (unsigned)b1 && sb == (unsigned)b2);
        }
        if (less) {
            int p = atomicAdd(&sh_nOut, 1);
            if (p < CTX) I[row * CTX + p] = i;
        } else if (eq) {
            int p = atomicAdd(&sh_nBuf, 1);
            if (p < CAPK) { bufKey[p] = k; bufIdx[p] = i; }
        }
    }
    __syncthreads();

    const int nOut = min(sh_nOut, CTX);
    const int bc   = min(sh_nBuf, CAPK);
    const int need = CTX - nOut;

    for (int it = 0; it < need; it++) {
        unsigned long long best = ~0ull;
        for (int i = t; i < bc; i += 256) {
            unsigned long long v = ((unsigned long long)bufKey[i] << 32) | (unsigned)i;
            if (v < best) best = v;
        }
        red[t] = best;
        __syncthreads();
        for (int s = 128; s > 0; s >>= 1) {
            if (t < s && red[t + s] < red[t]) red[t] = red[t + s];
            __syncthreads();
        }
        if (t == 0) {
            int p = (int)(red[0] & 0xffffffffu);
            I[row * CTX + nOut + it] = bufIdx[p];
            bufKey[p] = 0xFFFFFFFFu;
        }
        __syncthreads();
    }
}

// ---------------------------------------------------------------------------
// Gather ki, diff = k - ki, exact S = |diff|^2, labels.
// ---------------------------------------------------------------------------
__global__ void gather_diff(
    const float* __restrict__ kq, const float* __restrict__ ki,
    const int* __restrict__ I, const int* __restrict__ cy,
    float* __restrict__ diff, float* __restrict__ S, int* __restrict__ cls)
{
    const int bc = blockIdx.x;
    const int t  = threadIdx.x;
    const int b  = bc / CTX;
    const int idx = I[bc];
    float d = kq[(size_t)b * D + t] - ki[(size_t)idx * D + t];
    diff[(size_t)bc * D + t] = d;
    __shared__ float red[256];
    red[t] = d * d;
    __syncthreads();
    for (int k = 128; k > 0; k >>= 1) {
        if (t < k) red[t] += red[t + k];
        __syncthreads();
    }
    if (t == 0) { S[bc] = red[0]; cls[bc] = cy[idx]; }
}

// ---------------------------------------------------------------------------
// Softmax over CTX=96 per row
// ---------------------------------------------------------------------------
__global__ void softmax96(const float* __restrict__ S, float* __restrict__ w)
{
    const int b = blockIdx.x, t = threadIdx.x;
    __shared__ float red[128];
    float v = (t < CTX) ? S[b * CTX + t] : -INFINITY;
    red[t] = v;
    __syncthreads();
    for (int k = 64; k > 0; k >>= 1) {
        if (t < k) red[t] = fmaxf(red[t], red[t + k]);
        __syncthreads();
    }
    float mx = red[0];
    __syncthreads();
    float e = (t < CTX) ? expf(v - mx) : 0.f;
    red[t] = e;
    __syncthreads();
    for (int k = 64; k > 0; k >>= 1) {
        if (t < k) red[t] += red[t + k];
        __syncthreads();
    }
    float sm = red[0];
    if (t < CTX) w[b * CTX + t] = e / sm;
}

// ---------------------------------------------------------------------------
// xr = x + sum_c w * (V + Y_emb[cls])
// ---------------------------------------------------------------------------
__global__ void aggregate(
    const float* __restrict__ x, const float* __restrict__ w,
    const float* __restrict__ V, const int* __restrict__ cls,
    const float* __restrict__ Yemb, float* __restrict__ xo)
{
    const int b = blockIdx.x, t = threadIdx.x;
    float acc = x[b * D + t];
    const int base = b * CTX;
    for (int c = 0; c < CTX; c++) {
        float wv = w[base + c];
        int   cl = cls[base + c];
        acc += wv * (V[(size_t)(base + c) * D + t] + Yemb[cl * D + t]);
    }
    xo[b * D + t] = acc;
}

// ---------------------------------------------------------------------------
// LayerNorm over D=256 per row
// ---------------------------------------------------------------------------
__global__ void ln_kernel(
    const float* __restrict__ X, const float* __restrict__ sc,
    const float* __restrict__ bi, float* __restrict__ Y)
{
    const int b = blockIdx.x, t = threadIdx.x;
    float v = X[b * D + t];
    __shared__ float red[256];
    red[t] = v;
    __syncthreads();
    for (int k = 128; k > 0; k >>= 1) { if (t < k) red[t] += red[t + k]; __syncthreads(); }
    float m = red[0] * (1.f / D);
    __syncthreads();
    float dv = v - m;
    red[t] = dv * dv;
    __syncthreads();
    for (int k = 128; k > 0; k >>= 1) { if (t < k) red[t] += red[t + k]; __syncthreads(); }
    float var = red[0] * (1.f / D);
    Y[b * D + t] = dv * rsqrtf(var + 1e-5f) * sc[t] + bi[t];
}

// ---------------------------------------------------------------------------
// Head: out = relu(LN(x)) @ P_W + P_b
// ---------------------------------------------------------------------------
__global__ void head_kernel(
    const float* __restrict__ X, const float* __restrict__ sc,
    const float* __restrict__ bi, const float* __restrict__ PW,
    const float* __restrict__ Pb, float* __restrict__ out)
{
    const int b = blockIdx.x, t = threadIdx.x;
    float v = X[b * D + t];
    __shared__ float red[256];
    red[t] = v;
    __syncthreads();
    for (int k = 128; k > 0; k >>= 1) { if (t < k) red[t] += red[t + k]; __syncthreads(); }
    float m = red[0] * (1.f / D);
    __syncthreads();
    float dv = v - m;
    red[t] = dv * dv;
    __syncthreads();
    for (int k = 128; k > 0; k >>= 1) { if (t < k) red[t] += red[t + k]; __syncthreads(); }
    float var = red[0] * (1.f / D);
    __syncthreads();
    float h = fmaxf(dv * rsqrtf(var + 1e-5f) * sc[t] + bi[t], 0.f);
    for (int j = 0; j < NCLS; j++) {
        red[t] = h * PW[t * NCLS + j];
        __syncthreads();
        for (int k = 128; k > 0; k >>= 1) { if (t < k) red[t] += red[t + k]; __syncthreads(); }
        if (t == 0) out[b * NCLS + j] = red[0] + Pb[j];
        __syncthreads();
    }
}

// ---------------------------------------------------------------------------
// Launch
// ---------------------------------------------------------------------------
extern "C" void kernel_launch(void* const* d_in, const int* in_sizes, int n_in,
                              void* d_out, int out_size)
{
    (void)n_in; (void)out_size;
    const float* x_num    = (const float*)d_in[0];
    const float* cand_num = (const float*)d_in[1];
    const int*   cand_y   = (const int*)d_in[2];
    const int base = (in_sizes[3] == 1) ? 4 : 3;
    const float* W_lin   = (const float*)d_in[base + 0];
    const float* b_lin   = (const float*)d_in[base + 1];
    const float* W_K     = (const float*)d_in[base + 2];
    const float* b_K     = (const float*)d_in[base + 3];
    const float* Y_emb   = (const float*)d_in[base + 4];
    const float* T_W1    = (const float*)d_in[base + 5];
    const float* T_b1    = (const float*)d_in[base + 6];
    const float* T_W2    = (const float*)d_in[base + 7];
    const float* bp_ln_s = (const float*)d_in[base + 8];
    const float* bp_ln_b = (const float*)d_in[base + 9];
    const float* bp_W1   = (const float*)d_in[base + 10];
    const float* bp_b1   = (const float*)d_in[base + 11];
    const float* bp_W2   = (const float*)d_in[base + 12];
    const float* bp_b2   = (const float*)d_in[base + 13];
    const float* P_ln_s  = (const float*)d_in[base + 14];
    const float* P_ln_b  = (const float*)d_in[base + 15];
    const float* P_W     = (const float*)d_in[base + 16];
    const float* P_b     = (const float*)d_in[base + 17];
    float* out = (float*)d_out;

    float *h1, *ki, *nn2, *xb, *kb, *kk2, *d2, *diff, *mh, *Vb, *xr, *lnb, *p1, *x2;
    float *Sb, *wb;
    int *Ib, *clsb;
    cudaGetSymbolAddress((void**)&h1,  g_h1);
    cudaGetSymbolAddress((void**)&ki,  g_ki);
    cudaGetSymbolAddress((void**)&nn2, g_nn);
    cudaGetSymbolAddress((void**)&xb,  g_x);
    cudaGetSymbolAddress((void**)&kb,  g_k);
    cudaGetSymbolAddress((void**)&kk2, g_kk);
    cudaGetSymbolAddress((void**)&d2,  g_d2);
    cudaGetSymbolAddress((void**)&Ib,  g_I);
    cudaGetSymbolAddress((void**)&clsb,g_cls);
    cudaGetSymbolAddress((void**)&Sb,  g_S);
    cudaGetSymbolAddress((void**)&wb,  g_w);
    cudaGetSymbolAddress((void**)&diff,g_diff);
    cudaGetSymbolAddress((void**)&mh,  g_mh);
    cudaGetSymbolAddress((void**)&Vb,  g_V);
    cudaGetSymbolAddress((void**)&xr,  g_xr);
    cudaGetSymbolAddress((void**)&lnb, g_ln);
    cudaGetSymbolAddress((void**)&p1,  g_p1);
    cudaGetSymbolAddress((void**)&x2,  g_x2);

    const dim3 blk(256);

    // candidate projections
    sgemm_nn<<<dim3(D / 128, (NC + 127) / 128), blk>>>(NC, D, NF, cand_num, W_lin, b_lin, nullptr, h1, 0);
    sgemm_nn<<<dim3(D / 128, (NC + 127) / 128), blk>>>(NC, D, D,  h1,       W_K,   b_K,   nullptr, ki, 0);
    rownorm2<<<NC, 256>>>(ki, nn2);

    // query projections
    sgemm_nn<<<dim3(D / 128, Bq / 128), blk>>>(Bq, D, NF, x_num, W_lin, b_lin, nullptr, xb, 0);
    sgemm_nn<<<dim3(D / 128, Bq / 128), blk>>>(Bq, D, D,  xb,    W_K,   b_K,   nullptr, kb, 0);
    rownorm2<<<Bq, 256>>>(kb, kk2);

    // distance matrix + top-96
    dist_nt<<<dim3((NC + 127) / 128, Bq / 128), blk>>>(Bq, NC, D, kb, ki, kk2, nn2, d2);
    topk_kernel<<<Bq, 256>>>(d2, NC, Ib);

    // gather + softmax
    gather_diff<<<Bq * CTX, 256>>>(kb, ki, Ib, cand_y, diff, Sb, clsb);
    softmax96<<<Bq, 128>>>(Sb, wb);

    // T MLP
    sgemm_nn<<<dim3(DI / 128, (Bq * CTX) / 128), blk>>>(Bq * CTX, DI, D,  diff, T_W1, T_b1, nullptr, mh, 1);
    sgemm_nn<<<dim3(D / 128,  (Bq * CTX) / 128), blk>>>(Bq * CTX, D,  DI, mh,   T_W2, nullptr, nullptr, Vb, 0);

    // aggregation + residual
    aggregate<<<Bq, 256>>>(xb, wb, Vb, clsb, Y_emb, xr);

    // predictor block
    ln_kernel<<<Bq, 256>>>(xr, bp_ln_s, bp_ln_b, lnb);
    sgemm_nn<<<dim3(DI / 128, Bq / 128), blk>>>(Bq, DI, D,  lnb, bp_W1, bp_b1, nullptr, p1, 1);
    sgemm_nn<<<dim3(D / 128,  Bq / 128), blk>>>(Bq, D,  DI, p1,  bp_W2, bp_b2, xr,      x2, 0);

    // head
    head_kernel<<<Bq, 256>>>(x2, P_ln_s, P_ln_b, P_W, P_b, out);
}

// round 7
// speedup vs baseline: 1.0028x; 1.0028x over previous
#include <cuda_runtime.h>
#include <math.h>

// ---------------------------------------------------------------------------
// Problem constants
// ---------------------------------------------------------------------------
#define Bq    1024      // batch
#define NF    128       // n_feat
#define D     256       // d_main
#define DI    512       // d_int
#define NC    100000    // n candidates
#define CTX   96        // context size (top-k)
#define NCLS  10
#define CAPK  3584      // top-k candidate buffer capacity (smem)

// ---------------------------------------------------------------------------
// Device scratch
// ---------------------------------------------------------------------------
__device__ float g_h1  [(size_t)NC * D];
__device__ float g_ki  [(size_t)NC * D];
__device__ float g_nn  [NC];
__device__ float g_x   [Bq * D];
__device__ float g_k   [Bq * D];
__device__ float g_kk  [Bq];
__device__ float g_d2  [(size_t)Bq * NC];
__device__ int   g_I   [Bq * CTX];
__device__ int   g_cls [Bq * CTX];
__device__ float g_S   [Bq * CTX];
__device__ float g_w   [Bq * CTX];
__device__ float g_diff[(size_t)Bq * CTX * D];
__device__ float g_mh  [(size_t)Bq * CTX * DI];
__device__ float g_V   [(size_t)Bq * CTX * D];
__device__ float g_xr  [Bq * D];
__device__ float g_ln  [Bq * D];
__device__ float g_p1  [Bq * DI];
__device__ float g_x2  [Bq * D];

// ---------------------------------------------------------------------------
// Double-buffered SGEMM (NN): C = act(A[M,K] @ B[K,N] + bias + addsrc)
// BM=BN=128, BK=8, 256 threads, 8x8 per-thread, smem rows padded to 136
// floats (544B: 16B-aligned rows -> LDS.128 in the inner loop).
// K % 8 == 0, N % 128 == 0 (all NN uses: N=256/512). M guarded.
// ---------------------------------------------------------------------------
__global__ void __launch_bounds__(256) sgemm_nn(
    int M, int N, int K,
    const float* __restrict__ A, const float* __restrict__ Bm,
    const float* __restrict__ bias, const float* __restrict__ addsrc,
    float* __restrict__ C, int relu)
{
    __shared__ float As[2][8][136];
    __shared__ float Bs[2][8][136];
    const int t  = threadIdx.x;
    const int m0 = blockIdx.y * 128;
    const int n0 = blockIdx.x * 128;
    const int tx = t & 15, ty = t >> 4;
    const int arow = t >> 1, acol = (t & 1) * 4;
    const int brow = t >> 5, bcol = (t & 31) * 4;
    const int gm_a = m0 + arow;

    float acc[8][8];
#pragma unroll
    for (int i = 0; i < 8; i++)
#pragma unroll
        for (int j = 0; j < 8; j++) acc[i][j] = 0.f;

    // preload tile 0
    {
        float4 av = make_float4(0.f, 0.f, 0.f, 0.f);
        if (gm_a < M)
            av = *reinterpret_cast<const float4*>(A + (size_t)gm_a * K + acol);
        As[0][acol + 0][arow] = av.x; As[0][acol + 1][arow] = av.y;
        As[0][acol + 2][arow] = av.z; As[0][acol + 3][arow] = av.w;
        float4 bv = *reinterpret_cast<const float4*>(Bm + (size_t)brow * N + n0 + bcol);
        *reinterpret_cast<float4*>(&Bs[0][brow][bcol]) = bv;
    }
    __syncthreads();

    const int ntiles = K >> 3;
    int buf = 0;
    for (int tt = 0; tt < ntiles; tt++) {
        float4 avn = make_float4(0.f, 0.f, 0.f, 0.f);
        float4 bvn;
        const bool more = (tt + 1 < ntiles);
        if (more) {
            const int k0 = (tt + 1) << 3;
            if (gm_a < M)
                avn = *reinterpret_cast<const float4*>(A + (size_t)gm_a * K + k0 + acol);
            bvn = *reinterpret_cast<const float4*>(Bm + (size_t)(k0 + brow) * N + n0 + bcol);
        }

#pragma unroll
        for (int kk = 0; kk < 8; kk++) {
            float4 a0 = *reinterpret_cast<const float4*>(&As[buf][kk][ty * 8]);
            float4 a1 = *reinterpret_cast<const float4*>(&As[buf][kk][ty * 8 + 4]);
            float4 b0 = *reinterpret_cast<const float4*>(&Bs[buf][kk][tx * 8]);
            float4 b1 = *reinterpret_cast<const float4*>(&Bs[buf][kk][tx * 8 + 4]);
            float a[8] = {a0.x, a0.y, a0.z, a0.w, a1.x, a1.y, a1.z, a1.w};
            float b[8] = {b0.x, b0.y, b0.z, b0.w, b1.x, b1.y, b1.z, b1.w};
#pragma unroll
            for (int i = 0; i < 8; i++)
#pragma unroll
                for (int j = 0; j < 8; j++)
                    acc[i][j] = fmaf(a[i], b[j], acc[i][j]);
        }

        if (more) {
            const int nb = buf ^ 1;
            As[nb][acol + 0][arow] = avn.x; As[nb][acol + 1][arow] = avn.y;
            As[nb][acol + 2][arow] = avn.z; As[nb][acol + 3][arow] = avn.w;
            *reinterpret_cast<float4*>(&Bs[nb][brow][bcol]) = bvn;
            __syncthreads();
            buf = nb;
        }
    }

#pragma unroll
    for (int i = 0; i < 8; i++) {
        int gm = m0 + ty * 8 + i;
        if (gm >= M) continue;
#pragma unroll
        for (int j = 0; j < 8; j++) {
            int gn = n0 + tx * 8 + j;
            float v = acc[i][j];
            if (bias)   v += bias[gn];
            if (addsrc) v += addsrc[(size_t)gm * N + gn];
            if (relu)   v = fmaxf(v, 0.f);
            C[(size_t)gm * N + gn] = v;
        }
    }
}

// ---------------------------------------------------------------------------
// Double-buffered distance GEMM (NT):
// C[m,n] = |a_m|^2 + |b_n|^2 - 2 * dot(A[m,:], Bt[n,:])
// A: [M,K] row-major, Bt: [N,K] row-major. K % 8 == 0. M,N guarded.
// ---------------------------------------------------------------------------
__global__ void __launch_bounds__(256) dist_nt(
    int M, int N, int K,
    const float* __restrict__ A, const float* __restrict__ Bt,
    const float* __restrict__ an2, const float* __restrict__ bn2,
    float* __restrict__ C)
{
    __shared__ float As[2][8][136];
    __shared__ float Bs[2][8][136];
    const int t  = threadIdx.x;
    const int m0 = blockIdx.y * 128;
    const int n0 = blockIdx.x * 128;
    const int tx = t & 15, ty = t >> 4;
    const int arow = t >> 1, acol = (t & 1) * 4;
    const int brow = t >> 1, bcol = (t & 1) * 4;
    const int gm_a = m0 + arow;
    const int gn_b = n0 + brow;

    float acc[8][8];
#pragma unroll
    for (int i = 0; i < 8; i++)
#pragma unroll
        for (int j = 0; j < 8; j++) acc[i][j] = 0.f;

    // preload tile 0
    {
        float4 av = make_float4(0.f, 0.f, 0.f, 0.f);
        if (gm_a < M)
            av = *reinterpret_cast<const float4*>(A + (size_t)gm_a * K + acol);
        As[0][acol + 0][arow] = av.x; As[0][acol + 1][arow] = av.y;
        As[0][acol + 2][arow] = av.z; As[0][acol + 3][arow] = av.w;
        float4 bv = make_float4(0.f, 0.f, 0.f, 0.f);
        if (gn_b < N)
            bv = *reinterpret_cast<const float4*>(Bt + (size_t)gn_b * K + bcol);
        Bs[0][bcol + 0][brow] = bv.x; Bs[0][bcol + 1][brow] = bv.y;
        Bs[0][bcol + 2][brow] = bv.z; Bs[0][bcol + 3][brow] = bv.w;
    }
    __syncthreads();

    const int ntiles = K >> 3;
    int buf = 0;
    for (int tt = 0; tt < ntiles; tt++) {
        float4 avn = make_float4(0.f, 0.f, 0.f, 0.f);
        float4 bvn = make_float4(0.f, 0.f, 0.f, 0.f);
        const bool more = (tt + 1 < ntiles);
        if (more) {
            const int k0 = (tt + 1) << 3;
            if (gm_a < M)
                avn = *reinterpret_cast<const float4*>(A + (size_t)gm_a * K + k0 + acol);
            if (gn_b < N)
                bvn = *reinterpret_cast<const float4*>(Bt + (size_t)gn_b * K + k0 + bcol);
        }

#pragma unroll
        for (int kk = 0; kk < 8; kk++) {
            float4 a0 = *reinterpret_cast<const float4*>(&As[buf][kk][ty * 8]);
            float4 a1 = *reinterpret_cast<const float4*>(&As[buf][kk][ty * 8 + 4]);
            float4 b0 = *reinterpret_cast<const float4*>(&Bs[buf][kk][tx * 8]);
            float4 b1 = *reinterpret_cast<const float4*>(&Bs[buf][kk][tx * 8 + 4]);
            float a[8] = {a0.x, a0.y, a0.z, a0.w, a1.x, a1.y, a1.z, a1.w};
            float b[8] = {b0.x, b0.y, b0.z, b0.w, b1.x, b1.y, b1.z, b1.w};
#pragma unroll
            for (int i = 0; i < 8; i++)
#pragma unroll
                for (int j = 0; j < 8; j++)
                    acc[i][j] = fmaf(a[i], b[j], acc[i][j]);
        }

        if (more) {
            const int nb = buf ^ 1;
            As[nb][acol + 0][arow] = avn.x; As[nb][acol + 1][arow] = avn.y;
            As[nb][acol + 2][arow] = avn.z; As[nb][acol + 3][arow] = avn.w;
            Bs[nb][bcol + 0][brow] = bvn.x; Bs[nb][bcol + 1][brow] = bvn.y;
            Bs[nb][bcol + 2][brow] = bvn.z; Bs[nb][bcol + 3][brow] = bvn.w;
            __syncthreads();
            buf = nb;
        }
    }

#pragma unroll
    for (int i = 0; i < 8; i++) {
        int gm = m0 + ty * 8 + i;
        if (gm >= M) continue;
        float a2 = an2[gm];
#pragma unroll
        for (int j = 0; j < 8; j++) {
            int gn = n0 + tx * 8 + j;
            if (gn >= N) continue;
            C[(size_t)gm * N + gn] = a2 + bn2[gn] - 2.f * acc[i][j];
        }
    }
}

// ---------------------------------------------------------------------------
// Row squared norms
// ---------------------------------------------------------------------------
__global__ void rownorm2(const float* __restrict__ X, float* __restrict__ out)
{
    int r = blockIdx.x, t = threadIdx.x;
    float v = X[(size_t)r * D + t];
    __shared__ float red[256];
    red[t] = v * v;
    __syncthreads();
    for (int k = 128; k > 0; k >>= 1) {
        if (t < k) red[t] += red[t + k];
        __syncthreads();
    }
    if (t == 0) out[r] = red[0];
}

// ---------------------------------------------------------------------------
// Top-96 smallest per row via histogram radix-select (unchanged, correct).
// ---------------------------------------------------------------------------
__device__ __forceinline__ unsigned f2u(float f) {
    unsigned u = __float_as_uint(f);
    return (u & 0x80000000u) ? ~u : (u | 0x80000000u);
}

__global__ void __launch_bounds__(256) topk_kernel(
    const float* __restrict__ D2, int N, int* __restrict__ I)
{
    const int row = blockIdx.x;
    const float* __restrict__ drow = D2 + (size_t)row * N;
    const int t = threadIdx.x;

    __shared__ unsigned hist[4096];
    __shared__ unsigned bufKey[CAPK];
    __shared__ int      bufIdx[CAPK];
    __shared__ unsigned pref[256];
    __shared__ unsigned long long red[256];
    __shared__ int sh_b1, sh_b2, sh_before, sh_nOut, sh_nBuf;

    for (int i = t; i < 4096; i += 256) hist[i] = 0;
    __syncthreads();
    for (int i = t; i < N; i += 256)
        atomicAdd(&hist[f2u(drow[i]) >> 20], 1u);
    __syncthreads();

    unsigned ls = 0;
#pragma unroll
    for (int j = 0; j < 16; j++) ls += hist[t * 16 + j];
    pref[t] = ls;
    __syncthreads();
    if (t == 0) {
        unsigned run = 0;
        for (int i = 0; i < 256; i++) { unsigned s = pref[i]; pref[i] = run; run += s; }
    }
    __syncthreads();
    {
        unsigned run = pref[t];
#pragma unroll
        for (int j = 0; j < 16; j++) {
            unsigned c = hist[t * 16 + j];
            if (run <= 95u && 95u < run + c) { sh_b1 = t * 16 + j; sh_before = (int)run; }
            run += c;
        }
    }
    __syncthreads();
    const int b1 = sh_b1;
    int before = sh_before;
    const unsigned cnt_b1 = hist[b1];
    __syncthreads();

    const int use2 = (cnt_b1 > CAPK);
    int b2 = -1;
    if (use2) {
        hist[t] = 0;
        __syncthreads();
        for (int i = t; i < N; i += 256) {
            unsigned k = f2u(drow[i]);
            if ((int)(k >> 20) == b1) atomicAdd(&hist[(k >> 12) & 255u], 1u);
        }
        __syncthreads();
        if (t == 0) {
            unsigned run = 0;
            unsigned tgt = (unsigned)(95 - before);
            for (int i = 0; i < 256; i++) {
                unsigned c = hist[i];
                if (run <= tgt && tgt < run + c) { sh_b2 = i; sh_before = before + (int)run; break; }
                run += c;
            }
        }
        __syncthreads();
        b2 = sh_b2;
        before = sh_before;
    }

    if (t == 0) { sh_nOut = 0; sh_nBuf = 0; }
    __syncthreads();
    for (int i = t; i < N; i += 256) {
        unsigned k = f2u(drow[i]);
        unsigned hb = k >> 20;
        bool less, eq;
        if (!use2) {
            less = hb < (unsigned)b1; eq = (hb == (unsigned)b1);
        } else {
            unsigned sb = (k >> 12) & 255u;
            less = (hb < (unsigned)b1) || (hb == (unsigned)b1 && sb < (unsigned)b2);
            eq   = (hb == (unsigned)b1 && sb == (unsigned)b2);
        }
        if (less) {
            int p = atomicAdd(&sh_nOut, 1);
            if (p < CTX) I[row * CTX + p] = i;
        } else if (eq) {
            int p = atomicAdd(&sh_nBuf, 1);
            if (p < CAPK) { bufKey[p] = k; bufIdx[p] = i; }
        }
    }
    __syncthreads();

    const int nOut = min(sh_nOut, CTX);
    const int bc   = min(sh_nBuf, CAPK);
    const int need = CTX - nOut;

    for (int it = 0; it < need; it++) {
        unsigned long long best = ~0ull;
        for (int i = t; i < bc; i += 256) {
            unsigned long long v = ((unsigned long long)bufKey[i] << 32) | (unsigned)i;
            if (v < best) best = v;
        }
        red[t] = best;
        __syncthreads();
        for (int s = 128; s > 0; s >>= 1) {
            if (t < s && red[t + s] < red[t]) red[t] = red[t + s];
            __syncthreads();
        }
        if (t == 0) {
            int p = (int)(red[0] & 0xffffffffu);
            I[row * CTX + nOut + it] = bufIdx[p];
            bufKey[p] = 0xFFFFFFFFu;
        }
        __syncthreads();
    }
}

// ---------------------------------------------------------------------------
// Gather ki, diff = k - ki, exact S = |diff|^2, labels.
// ---------------------------------------------------------------------------
__global__ void gather_diff(
    const float* __restrict__ kq, const float* __restrict__ ki,
    const int* __restrict__ I, const int* __restrict__ cy,
    float* __restrict__ diff, float* __restrict__ S, int* __restrict__ cls)
{
    const int bc = blockIdx.x;
    const int t  = threadIdx.x;
    const int b  = bc / CTX;
    const int idx = I[bc];
    float d = kq[(size_t)b * D + t] - ki[(size_t)idx * D + t];
    diff[(size_t)bc * D + t] = d;
    __shared__ float red[256];
    red[t] = d * d;
    __syncthreads();
    for (int k = 128; k > 0; k >>= 1) {
        if (t < k) red[t] += red[t + k];
        __syncthreads();
    }
    if (t == 0) { S[bc] = red[0]; cls[bc] = cy[idx]; }
}

// ---------------------------------------------------------------------------
// Softmax over CTX=96 per row
// ---------------------------------------------------------------------------
__global__ void softmax96(const float* __restrict__ S, float* __restrict__ w)
{
    const int b = blockIdx.x, t = threadIdx.x;
    __shared__ float red[128];
    float v = (t < CTX) ? S[b * CTX + t] : -INFINITY;
    red[t] = v;
    __syncthreads();
    for (int k = 64; k > 0; k >>= 1) {
        if (t < k) red[t] = fmaxf(red[t], red[t + k]);
        __syncthreads();
    }
    float mx = red[0];
    __syncthreads();
    float e = (t < CTX) ? expf(v - mx) : 0.f;
    red[t] = e;
    __syncthreads();
    for (int k = 64; k > 0; k >>= 1) {
        if (t < k) red[t] += red[t + k];
        __syncthreads();
    }
    float sm = red[0];
    if (t < CTX) w[b * CTX + t] = e / sm;
}

// ---------------------------------------------------------------------------
// xr = x + sum_c w * (V + Y_emb[cls])
// ---------------------------------------------------------------------------
__global__ void aggregate(
    const float* __restrict__ x, const float* __restrict__ w,
    const float* __restrict__ V, const int* __restrict__ cls,
    const float* __restrict__ Yemb, float* __restrict__ xo)
{
    const int b = blockIdx.x, t = threadIdx.x;
    float acc = x[b * D + t];
    const int base = b * CTX;
    for (int c = 0; c < CTX; c++) {
        float wv = w[base + c];
        int   cl = cls[base + c];
        acc += wv * (V[(size_t)(base + c) * D + t] + Yemb[cl * D + t]);
    }
    xo[b * D + t] = acc;
}

// ---------------------------------------------------------------------------
// LayerNorm over D=256 per row
// ---------------------------------------------------------------------------
__global__ void ln_kernel(
    const float* __restrict__ X, const float* __restrict__ sc,
    const float* __restrict__ bi, float* __restrict__ Y)
{
    const int b = blockIdx.x, t = threadIdx.x;
    float v = X[b * D + t];
    __shared__ float red[256];
    red[t] = v;
    __syncthreads();
    for (int k = 128; k > 0; k >>= 1) { if (t < k) red[t] += red[t + k]; __syncthreads(); }
    float m = red[0] * (1.f / D);
    __syncthreads();
    float dv = v - m;
    red[t] = dv * dv;
    __syncthreads();
    for (int k = 128; k > 0; k >>= 1) { if (t < k) red[t] += red[t + k]; __syncthreads(); }
    float var = red[0] * (1.f / D);
    Y[b * D + t] = dv * rsqrtf(var + 1e-5f) * sc[t] + bi[t];
}

// ---------------------------------------------------------------------------
// Head: out = relu(LN(x)) @ P_W + P_b
// ---------------------------------------------------------------------------
__global__ void head_kernel(
    const float* __restrict__ X, const float* __restrict__ sc,
    const float* __restrict__ bi, const float* __restrict__ PW,
    const float* __restrict__ Pb, float* __restrict__ out)
{
    const int b = blockIdx.x, t = threadIdx.x;
    float v = X[b * D + t];
    __shared__ float red[256];
    red[t] = v;
    __syncthreads();
    for (int k = 128; k > 0; k >>= 1) { if (t < k) red[t] += red[t + k]; __syncthreads(); }
    float m = red[0] * (1.f / D);
    __syncthreads();
    float dv = v - m;
    red[t] = dv * dv;
    __syncthreads();
    for (int k = 128; k > 0; k >>= 1) { if (t < k) red[t] += red[t + k]; __syncthreads(); }
    float var = red[0] * (1.f / D);
    __syncthreads();
    float h = fmaxf(dv * rsqrtf(var + 1e-5f) * sc[t] + bi[t], 0.f);
    for (int j = 0; j < NCLS; j++) {
        red[t] = h * PW[t * NCLS + j];
        __syncthreads();
        for (int k = 128; k > 0; k >>= 1) { if (t < k) red[t] += red[t + k]; __syncthreads(); }
        if (t == 0) out[b * NCLS + j] = red[0] + Pb[j];
        __syncthreads();
    }
}

// ---------------------------------------------------------------------------
// Launch
// ---------------------------------------------------------------------------
extern "C" void kernel_launch(void* const* d_in, const int* in_sizes, int n_in,
                              void* d_out, int out_size)
{
    (void)n_in; (void)out_size;
    const float* x_num    = (const float*)d_in[0];
    const float* cand_num = (const float*)d_in[1];
    const int*   cand_y   = (const int*)d_in[2];
    const int base = (in_sizes[3] == 1) ? 4 : 3;
    const float* W_lin   = (const float*)d_in[base + 0];
    const float* b_lin   = (const float*)d_in[base + 1];
    const float* W_K     = (const float*)d_in[base + 2];
    const float* b_K     = (const float*)d_in[base + 3];
    const float* Y_emb   = (const float*)d_in[base + 4];
    const float* T_W1    = (const float*)d_in[base + 5];
    const float* T_b1    = (const float*)d_in[base + 6];
    const float* T_W2    = (const float*)d_in[base + 7];
    const float* bp_ln_s = (const float*)d_in[base + 8];
    const float* bp_ln_b = (const float*)d_in[base + 9];
    const float* bp_W1   = (const float*)d_in[base + 10];
    const float* bp_b1   = (const float*)d_in[base + 11];
    const float* bp_W2   = (const float*)d_in[base + 12];
    const float* bp_b2   = (const float*)d_in[base + 13];
    const float* P_ln_s  = (const float*)d_in[base + 14];
    const float* P_ln_b  = (const float*)d_in[base + 15];
    const float* P_W     = (const float*)d_in[base + 16];
    const float* P_b     = (const float*)d_in[base + 17];
    float* out = (float*)d_out;

    float *h1, *ki, *nn2, *xb, *kb, *kk2, *d2, *diff, *mh, *Vb, *xr, *lnb, *p1, *x2;
    float *Sb, *wb;
    int *Ib, *clsb;
    cudaGetSymbolAddress((void**)&h1,  g_h1);
    cudaGetSymbolAddress((void**)&ki,  g_ki);
    cudaGetSymbolAddress((void**)&nn2, g_nn);
    cudaGetSymbolAddress((void**)&xb,  g_x);
    cudaGetSymbolAddress((void**)&kb,  g_k);
    cudaGetSymbolAddress((void**)&kk2, g_kk);
    cudaGetSymbolAddress((void**)&d2,  g_d2);
    cudaGetSymbolAddress((void**)&Ib,  g_I);
    cudaGetSymbolAddress((void**)&clsb,g_cls);
    cudaGetSymbolAddress((void**)&Sb,  g_S);
    cudaGetSymbolAddress((void**)&wb,  g_w);
    cudaGetSymbolAddress((void**)&diff,g_diff);
    cudaGetSymbolAddress((void**)&mh,  g_mh);
    cudaGetSymbolAddress((void**)&Vb,  g_V);
    cudaGetSymbolAddress((void**)&xr,  g_xr);
    cudaGetSymbolAddress((void**)&lnb, g_ln);
    cudaGetSymbolAddress((void**)&p1,  g_p1);
    cudaGetSymbolAddress((void**)&x2,  g_x2);

    const dim3 blk(256);

    // candidate projections
    sgemm_nn<<<dim3(D / 128, (NC + 127) / 128), blk>>>(NC, D, NF, cand_num, W_lin, b_lin, nullptr, h1, 0);
    sgemm_nn<<<dim3(D / 128, (NC + 127) / 128), blk>>>(NC, D, D,  h1,       W_K,   b_K,   nullptr, ki, 0);
    rownorm2<<<NC, 256>>>(ki, nn2);

    // query projections
    sgemm_nn<<<dim3(D / 128, Bq / 128), blk>>>(Bq, D, NF, x_num, W_lin, b_lin, nullptr, xb, 0);
    sgemm_nn<<<dim3(D / 128, Bq / 128), blk>>>(Bq, D, D,  xb,    W_K,   b_K,   nullptr, kb, 0);
    rownorm2<<<Bq, 256>>>(kb, kk2);

    // distance matrix + top-96
    dist_nt<<<dim3((NC + 127) / 128, Bq / 128), blk>>>(Bq, NC, D, kb, ki, kk2, nn2, d2);
    topk_kernel<<<Bq, 256>>>(d2, NC, Ib);

    // gather + softmax
    gather_diff<<<Bq * CTX, 256>>>(kb, ki, Ib, cand_y, diff, Sb, clsb);
    softmax96<<<Bq, 128>>>(Sb, wb);

    // T MLP
    sgemm_nn<<<dim3(DI / 128, (Bq * CTX) / 128), blk>>>(Bq * CTX, DI, D,  diff, T_W1, T_b1, nullptr, mh, 1);
    sgemm_nn<<<dim3(D / 128,  (Bq * CTX) / 128), blk>>>(Bq * CTX, D,  DI, mh,   T_W2, nullptr, nullptr, Vb, 0);

    // aggregation + residual
    aggregate<<<Bq, 256>>>(xb, wb, Vb, clsb, Y_emb, xr);

    // predictor block
    ln_kernel<<<Bq, 256>>>(xr, bp_ln_s, bp_ln_b, lnb);
    sgemm_nn<<<dim3(DI / 128, Bq / 128), blk>>>(Bq, DI, D,  lnb, bp_W1, bp_b1, nullptr, p1, 1);
    sgemm_nn<<<dim3(D / 128,  Bq / 128), blk>>>(Bq, D,  DI, p1,  bp_W2, bp_b2, xr,      x2, 0);

    // head
    head_kernel<<<Bq, 256>>>(x2, P_ln_s, P_ln_b, P_W, P_b, out);
}

// round 9
// speedup vs baseline: 1.3104x; 1.3068x over previous
#include <cuda_runtime.h>
#include <cuda_bf16.h>
#include <math.h>
#include <stdint.h>

#define Bq    1024
#define NF    128
#define D     256
#define DI    512
#define NC    100000
#define CTX   96
#define KSEL  128      // approximate preselection size
#define NCLS  10
#define CAPK  3584

// ---------------------------------------------------------------------------
// Device scratch
// ---------------------------------------------------------------------------
__device__ float g_h1 [(size_t)NC * D];
__device__ float g_ki [(size_t)NC * D];
__device__ float g_nn [NC];
__device__ float g_x  [Bq * D];
__device__ float g_k  [Bq * D];
__device__ float g_kk [Bq];
__device__ float g_d2 [(size_t)Bq * NC];
__device__ float g_V  [(size_t)Bq * CTX * D];
__device__ float g_xr [Bq * D];
__device__ float g_ln [Bq * D];
__device__ float g_p1 [Bq * DI];
__device__ float g_x2 [Bq * D];
__device__ float g_S  [Bq * CTX];
__device__ float g_w  [Bq * CTX];
__device__ int   g_I2 [Bq * KSEL];
__device__ int   g_I  [Bq * CTX];
__device__ int   g_cls[Bq * CTX];
// bf16 split planes (h = bf16(x), l = bf16(x - h))
__device__ __nv_bfloat16 g_kbh[Bq * D],            g_kbl[Bq * D];
__device__ __nv_bfloat16 g_kih[(size_t)NC * D],    g_kil[(size_t)NC * D];
__device__ __nv_bfloat16 g_T1h[(size_t)DI * D],    g_T1l[(size_t)DI * D];
__device__ __nv_bfloat16 g_T2h[(size_t)D * DI],    g_T2l[(size_t)D * DI];
__device__ __nv_bfloat16 g_dfh[(size_t)Bq*CTX*D],  g_dfl[(size_t)Bq*CTX*D];
__device__ __nv_bfloat16 g_mhh[(size_t)Bq*CTX*DI], g_mhl[(size_t)Bq*CTX*DI];

// ---------------------------------------------------------------------------
// Warp MMA helpers (baseline PTX: ldmatrix sm_75+, mma.sync bf16 sm_80+)
// ---------------------------------------------------------------------------
__device__ __forceinline__ uint32_t smem_u32(const void* p) {
    uint32_t a;
    asm("{ .reg .u64 t; cvta.to.shared.u64 t, %1; cvt.u32.u64 %0, t; }" : "=r"(a) : "l"(p));
    return a;
}
__device__ __forceinline__ void ldm_x4(uint32_t* r, uint32_t addr) {
    asm volatile("ldmatrix.sync.aligned.m8n8.x4.shared.b16 {%0,%1,%2,%3}, [%4];"
                 : "=r"(r[0]), "=r"(r[1]), "=r"(r[2]), "=r"(r[3]) : "r"(addr));
}
__device__ __forceinline__ void mma16816(float* c, const uint32_t* a, uint32_t b0, uint32_t b1) {
    asm volatile(
        "mma.sync.aligned.m16n8k16.row.col.f32.bf16.bf16.f32 "
        "{%0,%1,%2,%3}, {%4,%5,%6,%7}, {%8,%9}, {%0,%1,%2,%3};"
        : "+f"(c[0]), "+f"(c[1]), "+f"(c[2]), "+f"(c[3])
        : "r"(a[0]), "r"(a[1]), "r"(a[2]), "r"(a[3]), "r"(b0), "r"(b1));
}

// ---------------------------------------------------------------------------
// Split bf16 NT GEMM on tensor cores:
// C[m,n] ~= sum_k A[m,k]*B[n,k], A=Ah+Al, B=Bh+Bl, products hh+hl+lh in fp32.
// Tile 128x128, BK=32, 256 threads (8 warps, each 32Mx64N).
// mode 0: Cf = an2[m]+bn2[n]-2*acc   (distance)
// mode 1: v = relu(acc + bias[n]); write split planes Ch/Cl
// mode 2: Cf = acc
// ---------------------------------------------------------------------------
#define SROW 40   // smem row stride in halves (80B: 16B-aligned, conflict-spread)

__global__ void __launch_bounds__(256) hmma_nt(
    int M, int N, int K,
    const __nv_bfloat16* __restrict__ A0, const __nv_bfloat16* __restrict__ A1,
    const __nv_bfloat16* __restrict__ B0, const __nv_bfloat16* __restrict__ B1,
    const float* __restrict__ bias, const float* __restrict__ an2,
    const float* __restrict__ bn2,
    float* __restrict__ Cf, __nv_bfloat16* __restrict__ Ch,
    __nv_bfloat16* __restrict__ Cl, int mode)
{
    __shared__ __align__(16) __nv_bfloat16 sA[2][128][SROW];
    __shared__ __align__(16) __nv_bfloat16 sB[2][128][SROW];

    const int t    = threadIdx.x;
    const int lane = t & 31;
    const int wid  = t >> 5;
    const int wm   = wid & 3;     // 4 M-blocks of 32
    const int wn   = wid >> 2;    // 2 N-blocks of 64
    const int m0   = blockIdx.y * 128;
    const int n0   = blockIdx.x * 128;

    float acc[2][8][4];
#pragma unroll
    for (int i = 0; i < 2; i++)
#pragma unroll
        for (int j = 0; j < 8; j++)
#pragma unroll
            for (int r = 0; r < 4; r++) acc[i][j][r] = 0.f;

    const __nv_bfloat16* Ap[2] = {A0, A1};
    const __nv_bfloat16* Bp[2] = {B0, B1};

    const int nchunk = K >> 5;
    for (int ch = 0; ch < nchunk; ch++) {
        const int k0 = ch << 5;
        // ---- stage 4 tile-planes: Ah, Al, Bh, Bl (each 128x32 bf16) ----
#pragma unroll
        for (int i = 0; i < 2; i++) {
            const int u   = t + 256 * i;       // 0..511
            const int row = u >> 2;
            const int q   = u & 3;             // 16B chunk within the 64B row
#pragma unroll
            for (int pl = 0; pl < 2; pl++) {
                uint4 va = make_uint4(0,0,0,0), vb = make_uint4(0,0,0,0);
                if (m0 + row < M)
                    va = *(const uint4*)(Ap[pl] + (size_t)(m0 + row) * K + k0 + q * 8);
                if (n0 + row < N)
                    vb = *(const uint4*)(Bp[pl] + (size_t)(n0 + row) * K + k0 + q * 8);
                *(uint4*)&sA[pl][row][q * 8] = va;
                *(uint4*)&sB[pl][row][q * 8] = vb;
            }
        }
        __syncthreads();

        // ---- compute: 2 k16 steps x 3 products ----
#pragma unroll
        for (int ks = 0; ks < 2; ks++) {
#pragma unroll
            for (int prod = 0; prod < 3; prod++) {
                const int ap = (prod == 2) ? 1 : 0;
                const int bp = (prod == 1) ? 1 : 0;
                // A fragments: 2 m16 tiles
                uint32_t af[2][4];
#pragma unroll
                for (int i = 0; i < 2; i++) {
                    const int arow = wm * 32 + i * 16 + (lane & 15);
                    const int acol = ks * 16 + (lane >> 4) * 8;
                    ldm_x4(af[i], smem_u32(&sA[ap][arow][acol]));
                }
                // B fragments: 4 x ldmatrix.x4, each covers two n8 tiles
                uint32_t bf[4][4];
#pragma unroll
                for (int j = 0; j < 4; j++) {
                    const int g  = lane >> 3;           // 0..3
                    const int lr = lane & 7;
                    const int brow = wn * 64 + j * 16 + ((g >> 1) ? 8 : 0) + lr;
                    const int bcol = ks * 16 + ((g & 1) ? 8 : 0);
                    ldm_x4(bf[j], smem_u32(&sB[bp][brow][bcol]));
                }
#pragma unroll
                for (int i = 0; i < 2; i++)
#pragma unroll
                    for (int j = 0; j < 8; j++)
                        mma16816(acc[i][j], af[i], bf[j >> 1][(j & 1) * 2],
                                 bf[j >> 1][(j & 1) * 2 + 1]);
            }
        }
        __syncthreads();
    }

    // ---- epilogue ----
    const int tq = lane >> 2;        // 0..7
    const int tr = lane & 3;         // 0..3
#pragma unroll
    for (int i = 0; i < 2; i++) {
#pragma unroll
        for (int j = 0; j < 8; j++) {
#pragma unroll
            for (int half = 0; half < 2; half++) {
                const int gm = m0 + wm * 32 + i * 16 + tq + half * 8;
                if (gm >= M) continue;
                const int gn = n0 + wn * 64 + j * 8 + tr * 2;
                const float v0 = acc[i][j][half * 2];
                const float v1 = acc[i][j][half * 2 + 1];
                if (mode == 0) {
                    const float a2 = an2[gm];
                    if (gn < N)     Cf[(size_t)gm * N + gn]     = a2 + bn2[gn]     - 2.f * v0;
                    if (gn + 1 < N) Cf[(size_t)gm * N + gn + 1] = a2 + bn2[gn + 1] - 2.f * v1;
                } else if (mode == 1) {
                    float r0 = fmaxf(v0 + bias[gn], 0.f);
                    float r1 = fmaxf(v1 + bias[gn + 1], 0.f);
                    __nv_bfloat16 h0 = __float2bfloat16(r0);
                    __nv_bfloat16 h1 = __float2bfloat16(r1);
                    Ch[(size_t)gm * N + gn]     = h0;
                    Ch[(size_t)gm * N + gn + 1] = h1;
                    Cl[(size_t)gm * N + gn]     = __float2bfloat16(r0 - __bfloat162float(h0));
                    Cl[(size_t)gm * N + gn + 1] = __float2bfloat16(r1 - __bfloat162float(h1));
                } else {
                    Cf[(size_t)gm * N + gn]     = v0;
                    Cf[(size_t)gm * N + gn + 1] = v1;
                }
            }
        }
    }
}

// ---------------------------------------------------------------------------
// fp32 FFMA SGEMM (NN) — exact path for projections / predictor
// ---------------------------------------------------------------------------
__global__ void __launch_bounds__(256) sgemm_nn(
    int M, int N, int K,
    const float* __restrict__ A, const float* __restrict__ Bm,
    const float* __restrict__ bias, const float* __restrict__ addsrc,
    float* __restrict__ C, int relu)
{
    __shared__ float As[8][132];
    __shared__ float Bs[8][132];
    const int t  = threadIdx.x;
    const int m0 = blockIdx.y * 128;
    const int n0 = blockIdx.x * 128;
    const int tx = t & 15, ty = t >> 4;
    const int arow = t >> 1, acol = (t & 1) * 4;
    const int brow = t >> 5, bcol = (t & 31) * 4;
    const int gm_a = m0 + arow;

    float acc[8][8];
#pragma unroll
    for (int i = 0; i < 8; i++)
#pragma unroll
        for (int j = 0; j < 8; j++) acc[i][j] = 0.f;

    for (int k0 = 0; k0 < K; k0 += 8) {
        float4 av = make_float4(0.f, 0.f, 0.f, 0.f);
        if (gm_a < M)
            av = *reinterpret_cast<const float4*>(A + (size_t)gm_a * K + k0 + acol);
        As[acol + 0][arow] = av.x; As[acol + 1][arow] = av.y;
        As[acol + 2][arow] = av.z; As[acol + 3][arow] = av.w;
        float4 bv = *reinterpret_cast<const float4*>(Bm + (size_t)(k0 + brow) * N + n0 + bcol);
        Bs[brow][bcol + 0] = bv.x; Bs[brow][bcol + 1] = bv.y;
        Bs[brow][bcol + 2] = bv.z; Bs[brow][bcol + 3] = bv.w;
        __syncthreads();
#pragma unroll
        for (int kk = 0; kk < 8; kk++) {
            float a[8], b[8];
#pragma unroll
            for (int i = 0; i < 8; i++) a[i] = As[kk][ty * 8 + i];
#pragma unroll
            for (int j = 0; j < 8; j++) b[j] = Bs[kk][tx * 8 + j];
#pragma unroll
            for (int i = 0; i < 8; i++)
#pragma unroll
                for (int j = 0; j < 8; j++)
                    acc[i][j] = fmaf(a[i], b[j], acc[i][j]);
        }
        __syncthreads();
    }
#pragma unroll
    for (int i = 0; i < 8; i++) {
        int gm = m0 + ty * 8 + i;
        if (gm >= M) continue;
#pragma unroll
        for (int j = 0; j < 8; j++) {
            int gn = n0 + tx * 8 + j;
            float v = acc[i][j];
            if (bias)   v += bias[gn];
            if (addsrc) v += addsrc[(size_t)gm * N + gn];
            if (relu)   v = fmaxf(v, 0.f);
            C[(size_t)gm * N + gn] = v;
        }
    }
}

// ---------------------------------------------------------------------------
// small utility kernels
// ---------------------------------------------------------------------------
__global__ void rownorm2(const float* __restrict__ X, float* __restrict__ out)
{
    int r = blockIdx.x, t = threadIdx.x;
    float v = X[(size_t)r * D + t];
    __shared__ float red[256];
    red[t] = v * v;
    __syncthreads();
    for (int k = 128; k > 0; k >>= 1) {
        if (t < k) red[t] += red[t + k];
        __syncthreads();
    }
    if (t == 0) out[r] = red[0];
}

__global__ void split2(const float* __restrict__ s,
                       __nv_bfloat16* __restrict__ h,
                       __nv_bfloat16* __restrict__ l, size_t n)
{
    size_t i = (size_t)blockIdx.x * blockDim.x + threadIdx.x;
    size_t stride = (size_t)gridDim.x * blockDim.x;
    for (; i < n; i += stride) {
        float v = s[i];
        __nv_bfloat16 vh = __float2bfloat16(v);
        h[i] = vh;
        l[i] = __float2bfloat16(v - __bfloat162float(vh));
    }
}

// W[K,N] row-major -> transposed split planes out[n*K + k]
__global__ void tsplit2(const float* __restrict__ W, int K, int N,
                        __nv_bfloat16* __restrict__ oh, __nv_bfloat16* __restrict__ ol)
{
    size_t total = (size_t)K * N;
    size_t i = (size_t)blockIdx.x * blockDim.x + threadIdx.x;
    size_t stride = (size_t)gridDim.x * blockDim.x;
    for (; i < total; i += stride) {
        int n = (int)(i / K), k = (int)(i % K);
        float v = W[(size_t)k * N + n];
        __nv_bfloat16 vh = __float2bfloat16(v);
        oh[i] = vh;
        ol[i] = __float2bfloat16(v - __bfloat162float(vh));
    }
}

// ---------------------------------------------------------------------------
// Top-ksel smallest per row (histogram radix-select; order arbitrary)
// ---------------------------------------------------------------------------
__device__ __forceinline__ unsigned f2u(float f) {
    unsigned u = __float_as_uint(f);
    return (u & 0x80000000u) ? ~u : (u | 0x80000000u);
}

__global__ void __launch_bounds__(256) topk_kernel(
    const float* __restrict__ D2, int N, int* __restrict__ I, int ksel)
{
    const int row = blockIdx.x;
    const float* __restrict__ drow = D2 + (size_t)row * N;
    const int t = threadIdx.x;
    const unsigned target = (unsigned)(ksel - 1);

    __shared__ unsigned hist[4096];
    __shared__ unsigned bufKey[CAPK];
    __shared__ int      bufIdx[CAPK];
    __shared__ unsigned pref[256];
    __shared__ unsigned long long red[256];
    __shared__ int sh_b1, sh_b2, sh_before, sh_nOut, sh_nBuf;

    for (int i = t; i < 4096; i += 256) hist[i] = 0;
    __syncthreads();
    for (int i = t; i < N; i += 256)
        atomicAdd(&hist[f2u(drow[i]) >> 20], 1u);
    __syncthreads();

    unsigned ls = 0;
#pragma unroll
    for (int j = 0; j < 16; j++) ls += hist[t * 16 + j];
    pref[t] = ls;
    __syncthreads();
    if (t == 0) {
        unsigned run = 0;
        for (int i = 0; i < 256; i++) { unsigned s = pref[i]; pref[i] = run; run += s; }
    }
    __syncthreads();
    {
        unsigned run = pref[t];
#pragma unroll
        for (int j = 0; j < 16; j++) {
            unsigned c = hist[t * 16 + j];
            if (run <= target && target < run + c) { sh_b1 = t * 16 + j; sh_before = (int)run; }
            run += c;
        }
    }
    __syncthreads();
    const int b1 = sh_b1;
    int before = sh_before;
    const unsigned cnt_b1 = hist[b1];
    __syncthreads();

    const int use2 = (cnt_b1 > CAPK);
    int b2 = -1;
    if (use2) {
        hist[t] = 0;
        __syncthreads();
        for (int i = t; i < N; i += 256) {
            unsigned k = f2u(drow[i]);
            if ((int)(k >> 20) == b1) atomicAdd(&hist[(k >> 12) & 255u], 1u);
        }
        __syncthreads();
        if (t == 0) {
            unsigned run = 0;
            unsigned tgt = target - (unsigned)before;
            for (int i = 0; i < 256; i++) {
                unsigned c = hist[i];
                if (run <= tgt && tgt < run + c) { sh_b2 = i; sh_before = before + (int)run; break; }
                run += c;
            }
        }
        __syncthreads();
        b2 = sh_b2;
        before = sh_before;
    }

    if (t == 0) { sh_nOut = 0; sh_nBuf = 0; }
    __syncthreads();
    for (int i = t; i < N; i += 256) {
        unsigned k = f2u(drow[i]);
        unsigned hb = k >> 20;
        bool less, eq;
        if (!use2) {
            less = hb < (unsigned)b1; eq = (hb == (unsigned)b1);
        } else {
            unsigned sb = (k >> 12) & 255u;
            less = (hb < (unsigned)b1) || (hb == (unsigned)b1 && sb < (unsigned)b2);
            eq   = (hb == (unsigned)b1 && sb == (unsigned)b2);
        }
        if (less) {
            int p = atomicAdd(&sh_nOut, 1);
            if (p < ksel) I[(size_t)row * ksel + p] = i;
        } else if (eq) {
            int p = atomicAdd(&sh_nBuf, 1);
            if (p < CAPK) { bufKey[p] = k; bufIdx[p] = i; }
        }
    }
    __syncthreads();

    const int nOut = min(sh_nOut, ksel);
    const int bc   = min(sh_nBuf, CAPK);
    const int need = ksel - nOut;

    for (int it = 0; it < need; it++) {
        unsigned long long best = ~0ull;
        for (int i = t; i < bc; i += 256) {
            unsigned long long v = ((unsigned long long)bufKey[i] << 32) | (unsigned)i;
            if (v < best) best = v;
        }
        red[t] = best;
        __syncthreads();
        for (int s = 128; s > 0; s >>= 1) {
            if (t < s && red[t + s] < red[t]) red[t] = red[t + s];
            __syncthreads();
        }
        if (t == 0) {
            int p = (int)(red[0] & 0xffffffffu);
            I[(size_t)row * ksel + nOut + it] = bufIdx[p];
            bufKey[p] = 0xFFFFFFFFu;
        }
        __syncthreads();
    }
}

// ---------------------------------------------------------------------------
// Rescore: exact fp32 expanded-form d2 for KSEL preselected candidates,
// exact rank-based top-96.
// ---------------------------------------------------------------------------
__global__ void __launch_bounds__(KSEL) rescore(
    const float* __restrict__ kb, const float* __restrict__ ki,
    const float* __restrict__ kk2, const float* __restrict__ nn2,
    const int* __restrict__ I2, int* __restrict__ I)
{
    const int row = blockIdx.x, t = threadIdx.x;
    __shared__ float q[D];
    __shared__ float key[KSEL];
    q[t]       = kb[(size_t)row * D + t];
    q[t + 128] = kb[(size_t)row * D + t + 128];
    __syncthreads();
    const int idx = I2[(size_t)row * KSEL + t];
    const float4* kr = (const float4*)(ki + (size_t)idx * D);
    float dot = 0.f;
#pragma unroll 8
    for (int j = 0; j < D / 4; j++) {
        float4 v = kr[j];
        dot += q[4*j+0]*v.x + q[4*j+1]*v.y + q[4*j+2]*v.z + q[4*j+3]*v.w;
    }
    const float s = kk2[row] - 2.f * dot + nn2[idx];
    key[t] = s;
    __syncthreads();
    int rank = 0;
    for (int j = 0; j < KSEL; j++) {
        float kj = key[j];
        rank += (kj < s) || (kj == s && j < t);
    }
    if (rank < CTX) I[(size_t)row * CTX + rank] = idx;
}

// ---------------------------------------------------------------------------
// Gather: diff = k - ki (bf16 split planes), exact S, labels.
// ---------------------------------------------------------------------------
__global__ void gather_diff(
    const float* __restrict__ kq, const float* __restrict__ ki,
    const int* __restrict__ I, const int* __restrict__ cy,
    __nv_bfloat16* __restrict__ dh, __nv_bfloat16* __restrict__ dl,
    float* __restrict__ S, int* __restrict__ cls)
{
    const int bc = blockIdx.x;
    const int t  = threadIdx.x;
    const int b  = bc / CTX;
    const int idx = I[bc];
    float d = kq[(size_t)b * D + t] - ki[(size_t)idx * D + t];
    __nv_bfloat16 h = __float2bfloat16(d);
    dh[(size_t)bc * D + t] = h;
    dl[(size_t)bc * D + t] = __float2bfloat16(d - __bfloat162float(h));
    __shared__ float red[256];
    red[t] = d * d;
    __syncthreads();
    for (int k = 128; k > 0; k >>= 1) {
        if (t < k) red[t] += red[t + k];
        __syncthreads();
    }
    if (t == 0) { S[bc] = red[0]; cls[bc] = cy[idx]; }
}

__global__ void softmax96(const float* __restrict__ S, float* __restrict__ w)
{
    const int b = blockIdx.x, t = threadIdx.x;
    __shared__ float red[128];
    float v = (t < CTX) ? S[b * CTX + t] : -INFINITY;
    red[t] = v;
    __syncthreads();
    for (int k = 64; k > 0; k >>= 1) {
        if (t < k) red[t] = fmaxf(red[t], red[t + k]);
        __syncthreads();
    }
    float mx = red[0];
    __syncthreads();
    float e = (t < CTX) ? expf(v - mx) : 0.f;
    red[t] = e;
    __syncthreads();
    for (int k = 64; k > 0; k >>= 1) {
        if (t < k) red[t] += red[t + k];
        __syncthreads();
    }
    float sm = red[0];
    if (t < CTX) w[b * CTX + t] = e / sm;
}

__global__ void aggregate(
    const float* __restrict__ x, const float* __restrict__ w,
    const float* __restrict__ V, const int* __restrict__ cls,
    const float* __restrict__ Yemb, float* __restrict__ xo)
{
    const int b = blockIdx.x, t = threadIdx.x;
    float acc = x[b * D + t];
    const int base = b * CTX;
    for (int c = 0; c < CTX; c++) {
        float wv = w[base + c];
        int   cl = cls[base + c];
        acc += wv * (V[(size_t)(base + c) * D + t] + Yemb[cl * D + t]);
    }
    xo[b * D + t] = acc;
}

__global__ void ln_kernel(
    const float* __restrict__ X, const float* __restrict__ sc,
    const float* __restrict__ bi, float* __restrict__ Y)
{
    const int b = blockIdx.x, t = threadIdx.x;
    float v = X[b * D + t];
    __shared__ float red[256];
    red[t] = v;
    __syncthreads();
    for (int k = 128; k > 0; k >>= 1) { if (t < k) red[t] += red[t + k]; __syncthreads(); }
    float m = red[0] * (1.f / D);
    __syncthreads();
    float dv = v - m;
    red[t] = dv * dv;
    __syncthreads();
    for (int k = 128; k > 0; k >>= 1) { if (t < k) red[t] += red[t + k]; __syncthreads(); }
    float var = red[0] * (1.f / D);
    Y[b * D + t] = dv * rsqrtf(var + 1e-5f) * sc[t] + bi[t];
}

__global__ void head_kernel(
    const float* __restrict__ X, const float* __restrict__ sc,
    const float* __restrict__ bi, const float* __restrict__ PW,
    const float* __restrict__ Pb, float* __restrict__ out)
{
    const int b = blockIdx.x, t = threadIdx.x;
    float v = X[b * D + t];
    __shared__ float red[256];
    red[t] = v;
    __syncthreads();
    for (int k = 128; k > 0; k >>= 1) { if (t < k) red[t] += red[t + k]; __syncthreads(); }
    float m = red[0] * (1.f / D);
    __syncthreads();
    float dv = v - m;
    red[t] = dv * dv;
    __syncthreads();
    for (int k = 128; k > 0; k >>= 1) { if (t < k) red[t] += red[t + k]; __syncthreads(); }
    float var = red[0] * (1.f / D);
    __syncthreads();
    float h = fmaxf(dv * rsqrtf(var + 1e-5f) * sc[t] + bi[t], 0.f);
    for (int j = 0; j < NCLS; j++) {
        red[t] = h * PW[t * NCLS + j];
        __syncthreads();
        for (int k = 128; k > 0; k >>= 1) { if (t < k) red[t] += red[t + k]; __syncthreads(); }
        if (t == 0) out[b * NCLS + j] = red[0] + Pb[j];
        __syncthreads();
    }
}

// ---------------------------------------------------------------------------
// Launch
// ---------------------------------------------------------------------------
extern "C" void kernel_launch(void* const* d_in, const int* in_sizes, int n_in,
                              void* d_out, int out_size)
{
    (void)n_in; (void)out_size;
    const float* x_num    = (const float*)d_in[0];
    const float* cand_num = (const float*)d_in[1];
    const int*   cand_y   = (const int*)d_in[2];
    const int base = (in_sizes[3] == 1) ? 4 : 3;
    const float* W_lin   = (const float*)d_in[base + 0];
    const float* b_lin   = (const float*)d_in[base + 1];
    const float* W_K     = (const float*)d_in[base + 2];
    const float* b_K     = (const float*)d_in[base + 3];
    const float* Y_emb   = (const float*)d_in[base + 4];
    const float* T_W1    = (const float*)d_in[base + 5];
    const float* T_b1    = (const float*)d_in[base + 6];
    const float* T_W2    = (const float*)d_in[base + 7];
    const float* bp_ln_s = (const float*)d_in[base + 8];
    const float* bp_ln_b = (const float*)d_in[base + 9];
    const float* bp_W1   = (const float*)d_in[base + 10];
    const float* bp_b1   = (const float*)d_in[base + 11];
    const float* bp_W2   = (const float*)d_in[base + 12];
    const float* bp_b2   = (const float*)d_in[base + 13];
    const float* P_ln_s  = (const float*)d_in[base + 14];
    const float* P_ln_b  = (const float*)d_in[base + 15];
    const float* P_W     = (const float*)d_in[base + 16];
    const float* P_b     = (const float*)d_in[base + 17];
    float* out = (float*)d_out;

    float *h1, *ki, *nn2, *xb, *kb, *kk2, *d2, *Vb, *xr, *lnb, *p1, *x2, *Sb, *wb;
    int *I2b, *Ib, *clsb;
    __nv_bfloat16 *kbh, *kbl, *kih, *kil, *T1h, *T1l, *T2h, *T2l, *dfh, *dfl, *mhh, *mhl;
    cudaGetSymbolAddress((void**)&h1,  g_h1);
    cudaGetSymbolAddress((void**)&ki,  g_ki);
    cudaGetSymbolAddress((void**)&nn2, g_nn);
    cudaGetSymbolAddress((void**)&xb,  g_x);
    cudaGetSymbolAddress((void**)&kb,  g_k);
    cudaGetSymbolAddress((void**)&kk2, g_kk);
    cudaGetSymbolAddress((void**)&d2,  g_d2);
    cudaGetSymbolAddress((void**)&Vb,  g_V);
    cudaGetSymbolAddress((void**)&xr,  g_xr);
    cudaGetSymbolAddress((void**)&lnb, g_ln);
    cudaGetSymbolAddress((void**)&p1,  g_p1);
    cudaGetSymbolAddress((void**)&x2,  g_x2);
    cudaGetSymbolAddress((void**)&Sb,  g_S);
    cudaGetSymbolAddress((void**)&wb,  g_w);
    cudaGetSymbolAddress((void**)&I2b, g_I2);
    cudaGetSymbolAddress((void**)&Ib,  g_I);
    cudaGetSymbolAddress((void**)&clsb,g_cls);
    cudaGetSymbolAddress((void**)&kbh, g_kbh); cudaGetSymbolAddress((void**)&kbl, g_kbl);
    cudaGetSymbolAddress((void**)&kih, g_kih); cudaGetSymbolAddress((void**)&kil, g_kil);
    cudaGetSymbolAddress((void**)&T1h, g_T1h); cudaGetSymbolAddress((void**)&T1l, g_T1l);
    cudaGetSymbolAddress((void**)&T2h, g_T2h); cudaGetSymbolAddress((void**)&T2l, g_T2l);
    cudaGetSymbolAddress((void**)&dfh, g_dfh); cudaGetSymbolAddress((void**)&dfl, g_dfl);
    cudaGetSymbolAddress((void**)&mhh, g_mhh); cudaGetSymbolAddress((void**)&mhl, g_mhl);

    const dim3 blk(256);

    // exact fp32 projections (selection-critical)
    sgemm_nn<<<dim3(D / 128, (NC + 127) / 128), blk>>>(NC, D, NF, cand_num, W_lin, b_lin, nullptr, h1, 0);
    sgemm_nn<<<dim3(D / 128, (NC + 127) / 128), blk>>>(NC, D, D,  h1,       W_K,   b_K,   nullptr, ki, 0);
    rownorm2<<<NC, 256>>>(ki, nn2);
    sgemm_nn<<<dim3(D / 128, Bq / 128), blk>>>(Bq, D, NF, x_num, W_lin, b_lin, nullptr, xb, 0);
    sgemm_nn<<<dim3(D / 128, Bq / 128), blk>>>(Bq, D, D,  xb,    W_K,   b_K,   nullptr, kb, 0);
    rownorm2<<<Bq, 256>>>(kb, kk2);

    // bf16 split planes for tensor-core GEMMs
    split2<<<4096, 256>>>(ki, kih, kil, (size_t)NC * D);
    split2<<<256,  256>>>(kb, kbh, kbl, (size_t)Bq * D);
    tsplit2<<<512, 256>>>(T_W1, D,  DI, T1h, T1l);
    tsplit2<<<512, 256>>>(T_W2, DI, D,  T2h, T2l);

    // tensor-core distance (approx) -> top-128 -> exact fp32 rescore -> top-96
    hmma_nt<<<dim3((NC + 127) / 128, Bq / 128), blk>>>(
        Bq, NC, D, kbh, kbl, kih, kil, nullptr, kk2, nn2, d2, nullptr, nullptr, 0);
    topk_kernel<<<Bq, 256>>>(d2, NC, I2b, KSEL);
    rescore<<<Bq, KSEL>>>(kb, ki, kk2, nn2, I2b, Ib);

    // gather (exact S + diff splits) + softmax
    gather_diff<<<Bq * CTX, 256>>>(kb, ki, Ib, cand_y, dfh, dfl, Sb, clsb);
    softmax96<<<Bq, 128>>>(Sb, wb);

    // tensor-core T-MLP
    hmma_nt<<<dim3(DI / 128, (Bq * CTX) / 128), blk>>>(
        Bq * CTX, DI, D, dfh, dfl, T1h, T1l, T_b1, nullptr, nullptr,
        nullptr, mhh, mhl, 1);
    hmma_nt<<<dim3(D / 128, (Bq * CTX) / 128), blk>>>(
        Bq * CTX, D, DI, mhh, mhl, T2h, T2l, nullptr, nullptr, nullptr,
        Vb, nullptr, nullptr, 2);

    // aggregation + predictor + head (exact fp32)
    aggregate<<<Bq, 256>>>(xb, wb, Vb, clsb, Y_emb, xr);
    ln_kernel<<<Bq, 256>>>(xr, bp_ln_s, bp_ln_b, lnb);
    sgemm_nn<<<dim3(DI / 128, Bq / 128), blk>>>(Bq, DI, D,  lnb, bp_W1, bp_b1, nullptr, p1, 1);
    sgemm_nn<<<dim3(D / 128,  Bq / 128), blk>>>(Bq, D,  DI, p1,  bp_W2, bp_b2, xr,      x2, 0);
    head_kernel<<<Bq, 256>>>(x2, P_ln_s, P_ln_b, P_W, P_b, out);
}